// round 1
// baseline (speedup 1.0000x reference)
#include <cuda_runtime.h>
#include <cuda_bf16.h>
#include <cstdint>

// Problem constants
#define B_   8
#define C_   256
#define HW_  16384          // 128*128
#define CHW_ (C_ * HW_)     // 4,194,304
#define EPSN 1e-5f

// ---------------- device scratch (no cudaMalloc allowed) ----------------
__device__ float g_sum  [B_ * C_];
__device__ float g_sumsq[B_ * C_];
__device__ float g_rin  [B_ * C_];
__device__ float g_muin [B_ * C_];
__device__ float g_rln  [B_];
__device__ float g_muln [B_];
__device__ float g_M    [B_ * C_ * C_];   // fused per-batch weight, gamma folded in
__device__ float g_d    [B_ * C_];        // fused per-batch bias (gamma,beta folded)

// ---------------- helpers ----------------
__device__ __forceinline__ float blockReduceSum(float v) {
    __shared__ float sh[8];
    int lane = threadIdx.x & 31, wid = threadIdx.x >> 5;
    #pragma unroll
    for (int o = 16; o; o >>= 1) v += __shfl_down_sync(0xffffffffu, v, o);
    if (!lane) sh[wid] = v;
    __syncthreads();
    if (wid == 0) {
        v = (lane < 8) ? sh[lane] : 0.0f;
        #pragma unroll
        for (int o = 4; o; o >>= 1) v += __shfl_down_sync(0xffffffffu, v, o);
    }
    __syncthreads();   // protect sh reuse across successive calls
    return v;          // valid in thread 0
}

// packed fp32x2 FMA (Blackwell packed-FP32 path; 2x MACs per instruction)
__device__ __forceinline__ unsigned long long bcast2(float a) {
    unsigned long long r;
    asm("mov.b64 %0, {%1, %1};" : "=l"(r) : "f"(a));
    return r;
}
__device__ __forceinline__ unsigned long long pack2(float lo, float hi) {
    unsigned long long r;
    asm("mov.b64 %0, {%1, %2};" : "=l"(r) : "f"(lo), "f"(hi));
    return r;
}
__device__ __forceinline__ void fma2(unsigned long long &d,
                                     unsigned long long a,
                                     unsigned long long b) {
    asm("fma.rn.f32x2 %0, %1, %2, %0;" : "+l"(d) : "l"(a), "l"(b));
}
union U64F2 { unsigned long long u; float2 f; };

// ---------------- kernel 1: per-(b,c) sum / sumsq ----------------
__global__ __launch_bounds__(256) void stats_kernel(const float* __restrict__ x) {
    int bc = blockIdx.x;                       // 0 .. B*C-1
    const float4* p = reinterpret_cast<const float4*>(x + (size_t)bc * HW_);
    float s = 0.f, ss = 0.f;
    for (int i = threadIdx.x; i < HW_ / 4; i += 256) {
        float4 v = p[i];
        s  += v.x + v.y + v.z + v.w;
        ss += v.x * v.x + v.y * v.y + v.z * v.z + v.w * v.w;
    }
    float ts  = blockReduceSum(s);
    float tss = blockReduceSum(ss);
    if (threadIdx.x == 0) { g_sum[bc] = ts; g_sumsq[bc] = tss; }
}

// ---------------- kernel 2a: per-channel + per-batch stats ----------------
__global__ __launch_bounds__(256) void batch_stats_kernel() {
    int b = blockIdx.x, c = threadIdx.x;
    float s  = g_sum  [b * C_ + c];
    float ss = g_sumsq[b * C_ + c];
    const float invHW = 1.0f / (float)HW_;
    float mu  = s * invHW;
    float var = ss * invHW - mu * mu;
    g_muin[b * C_ + c] = mu;
    g_rin [b * C_ + c] = rsqrtf(var + EPSN);

    float ts  = blockReduceSum(s);
    float tss = blockReduceSum(ss);
    if (threadIdx.x == 0) {
        const float invCHW = 1.0f / (float)CHW_;
        float muln  = ts * invCHW;
        float varln = tss * invCHW - muln * muln;
        g_muln[b] = muln;
        g_rln [b] = rsqrtf(varln + EPSN);
    }
}

// ---------------- kernel 2b: build fused M[b] and bias d[b] ----------------
__global__ __launch_bounds__(256) void build_M_kernel(const float* __restrict__ params,
                                                      const float* __restrict__ W) {
    int bo = blockIdx.x;              // b*C + o
    int b  = bo >> 8, o = bo & 255;
    int i  = threadIdx.x;

    float w1   = W[o * (2 * C_) + i];
    float w2   = W[o * (2 * C_) + C_ + i];
    float rin  = g_rin [b * C_ + i];
    float muin = g_muin[b * C_ + i];
    float rln  = g_rln [b];
    float muln = g_muln[b];
    float gamma = params[b * (2 * C_) + o];
    float beta  = params[b * (2 * C_) + C_ + o];

    float t = w1 * rin;
    g_M[(size_t)bo * C_ + i] = gamma * (t + w2 * rln);

    float pb = -(t * muin + w2 * rln * muln);
    float tot = blockReduceSum(pb);
    if (threadIdx.x == 0) g_d[bo] = gamma * tot + beta;
}

// ---------------- kernel 3: batched GEMM  out[b] = M[b] * x[b] + d[b] ----------------
#define BM 128
#define BN 128
#define BK 16
#define ASTR 136   // padded stride (16B aligned, conflict-free)

__global__ __launch_bounds__(256, 2) void gemm_kernel(const float* __restrict__ x,
                                                      float* __restrict__ out) {
    __shared__ float As[2][BK][ASTR];
    __shared__ float Bs[2][BK][BN];

    const int b  = blockIdx.z;
    const int mt = blockIdx.y;
    const int nt = blockIdx.x;
    const int t  = threadIdx.x;
    const int tx = t & 15;      // n-direction
    const int ty = t >> 4;      // m-direction

    const float* Ab = g_M + ((size_t)b * C_ + mt * BM) * C_;
    const float* Bb = x   + (size_t)b * CHW_ + (size_t)nt * BN;

    float4 ra[2], rb[2];

    auto loadA = [&](int kt) {
        #pragma unroll
        for (int j = 0; j < 2; j++) {
            int idx = t + 256 * j;
            int row = idx >> 2, c4 = idx & 3;
            ra[j] = *reinterpret_cast<const float4*>(Ab + (size_t)row * C_ + kt * BK + c4 * 4);
        }
    };
    auto loadB = [&](int kt) {
        #pragma unroll
        for (int j = 0; j < 2; j++) {
            int idx = t + 256 * j;
            int row = idx >> 5, c4 = idx & 31;
            rb[j] = *reinterpret_cast<const float4*>(Bb + (size_t)(kt * BK + row) * HW_ + c4 * 4);
        }
    };
    auto storeAB = [&](int buf) {
        #pragma unroll
        for (int j = 0; j < 2; j++) {
            int idx = t + 256 * j;
            int row = idx >> 2, c4 = idx & 3;
            As[buf][c4 * 4 + 0][row] = ra[j].x;
            As[buf][c4 * 4 + 1][row] = ra[j].y;
            As[buf][c4 * 4 + 2][row] = ra[j].z;
            As[buf][c4 * 4 + 3][row] = ra[j].w;
        }
        #pragma unroll
        for (int j = 0; j < 2; j++) {
            int idx = t + 256 * j;
            int row = idx >> 5, c4 = idx & 31;
            *reinterpret_cast<float4*>(&Bs[buf][row][c4 * 4]) = rb[j];
        }
    };

    loadA(0); loadB(0);
    storeAB(0);
    __syncthreads();

    unsigned long long acc[8][4];
    #pragma unroll
    for (int m = 0; m < 8; m++)
        #pragma unroll
        for (int p = 0; p < 4; p++) acc[m][p] = 0ULL;

    int cur = 0;
    const int NKT = C_ / BK;   // 16
    for (int kt = 0; kt < NKT; kt++) {
        if (kt + 1 < NKT) { loadA(kt + 1); loadB(kt + 1); }

        #pragma unroll
        for (int kk = 0; kk < BK; kk++) {
            float4 a0 = *reinterpret_cast<const float4*>(&As[cur][kk][ty * 8]);
            float4 a1 = *reinterpret_cast<const float4*>(&As[cur][kk][ty * 8 + 4]);
            float4 b0 = *reinterpret_cast<const float4*>(&Bs[cur][kk][tx * 8]);
            float4 b1 = *reinterpret_cast<const float4*>(&Bs[cur][kk][tx * 8 + 4]);

            unsigned long long bp0 = pack2(b0.x, b0.y);
            unsigned long long bp1 = pack2(b0.z, b0.w);
            unsigned long long bp2 = pack2(b1.x, b1.y);
            unsigned long long bp3 = pack2(b1.z, b1.w);

            float am[8] = {a0.x, a0.y, a0.z, a0.w, a1.x, a1.y, a1.z, a1.w};
            #pragma unroll
            for (int m = 0; m < 8; m++) {
                unsigned long long a2 = bcast2(am[m]);
                fma2(acc[m][0], a2, bp0);
                fma2(acc[m][1], a2, bp1);
                fma2(acc[m][2], a2, bp2);
                fma2(acc[m][3], a2, bp3);
            }
        }

        if (kt + 1 < NKT) {
            __syncthreads();
            storeAB(cur ^ 1);
            __syncthreads();
            cur ^= 1;
        }
    }

    // epilogue: add fused bias, store
    const int o0  = mt * BM + ty * 8;
    const int n0g = nt * BN + tx * 8;
    float* outp = out + (size_t)b * CHW_;
    #pragma unroll
    for (int m = 0; m < 8; m++) {
        float dv = g_d[b * C_ + o0 + m];
        U64F2 u0, u1, u2, u3;
        u0.u = acc[m][0]; u1.u = acc[m][1]; u2.u = acc[m][2]; u3.u = acc[m][3];
        float4 v0 = make_float4(u0.f.x + dv, u0.f.y + dv, u1.f.x + dv, u1.f.y + dv);
        float4 v1 = make_float4(u2.f.x + dv, u2.f.y + dv, u3.f.x + dv, u3.f.y + dv);
        float* rowp = outp + (size_t)(o0 + m) * HW_ + n0g;
        *reinterpret_cast<float4*>(rowp)     = v0;
        *reinterpret_cast<float4*>(rowp + 4) = v1;
    }
}

// ---------------- launcher ----------------
extern "C" void kernel_launch(void* const* d_in, const int* in_sizes, int n_in,
                              void* d_out, int out_size) {
    const float* x      = (const float*)d_in[0];   // [8,256,128,128]
    const float* params = (const float*)d_in[1];   // [8,512]
    const float* W      = (const float*)d_in[2];   // [256,512]
    float* out          = (float*)d_out;           // [8,256,128,128]

    stats_kernel      <<<B_ * C_, 256>>>(x);
    batch_stats_kernel<<<B_,      256>>>();
    build_M_kernel    <<<B_ * C_, 256>>>(params, W);

    dim3 grid(HW_ / BN, C_ / BM, B_);              // (128, 2, 8)
    gemm_kernel<<<grid, 256>>>(x, out);
}

// round 2
// speedup vs baseline: 1.7857x; 1.7857x over previous
#include <cuda_runtime.h>
#include <cuda_bf16.h>
#include <cstdint>

// Problem constants
#define B_   8
#define C_   256
#define HW_  16384          // 128*128
#define CHW_ (C_ * HW_)     // 4,194,304
#define EPSN 1e-5f

// ---------------- device scratch (no cudaMalloc allowed) ----------------
__device__ float g_sum  [B_ * C_];
__device__ float g_sumsq[B_ * C_];
__device__ float g_rin  [B_ * C_];
__device__ float g_muin [B_ * C_];
__device__ float g_rln  [B_];
__device__ float g_muln [B_];
__device__ float g_M    [B_ * C_ * C_];   // fused per-batch weight, gamma folded in
__device__ float g_d    [B_ * C_];        // fused per-batch bias (gamma,beta folded)

// ---------------- helpers ----------------
__device__ __forceinline__ float blockReduceSum(float v) {
    __shared__ float sh[8];
    int lane = threadIdx.x & 31, wid = threadIdx.x >> 5;
    #pragma unroll
    for (int o = 16; o; o >>= 1) v += __shfl_down_sync(0xffffffffu, v, o);
    if (!lane) sh[wid] = v;
    __syncthreads();
    if (wid == 0) {
        v = (lane < 8) ? sh[lane] : 0.0f;
        #pragma unroll
        for (int o = 4; o; o >>= 1) v += __shfl_down_sync(0xffffffffu, v, o);
    }
    __syncthreads();
    return v;          // valid in thread 0
}

// ---------------- kernel 1: per-(b,c) sum / sumsq ----------------
__global__ __launch_bounds__(256) void stats_kernel(const float* __restrict__ x) {
    int bc = blockIdx.x;
    const float4* p = reinterpret_cast<const float4*>(x + (size_t)bc * HW_);
    float s = 0.f, ss = 0.f;
    for (int i = threadIdx.x; i < HW_ / 4; i += 256) {
        float4 v = p[i];
        s  += v.x + v.y + v.z + v.w;
        ss += v.x * v.x + v.y * v.y + v.z * v.z + v.w * v.w;
    }
    float ts  = blockReduceSum(s);
    float tss = blockReduceSum(ss);
    if (threadIdx.x == 0) { g_sum[bc] = ts; g_sumsq[bc] = tss; }
}

// ---------------- kernel 2a: per-channel + per-batch stats ----------------
__global__ __launch_bounds__(256) void batch_stats_kernel() {
    int b = blockIdx.x, c = threadIdx.x;
    float s  = g_sum  [b * C_ + c];
    float ss = g_sumsq[b * C_ + c];
    const float invHW = 1.0f / (float)HW_;
    float mu  = s * invHW;
    float var = ss * invHW - mu * mu;
    g_muin[b * C_ + c] = mu;
    g_rin [b * C_ + c] = rsqrtf(var + EPSN);

    float ts  = blockReduceSum(s);
    float tss = blockReduceSum(ss);
    if (threadIdx.x == 0) {
        const float invCHW = 1.0f / (float)CHW_;
        float muln  = ts * invCHW;
        float varln = tss * invCHW - muln * muln;
        g_muln[b] = muln;
        g_rln [b] = rsqrtf(varln + EPSN);
    }
}

// ---------------- kernel 2b: build fused M[b] and bias d[b] ----------------
__global__ __launch_bounds__(256) void build_M_kernel(const float* __restrict__ params,
                                                      const float* __restrict__ W) {
    int bo = blockIdx.x;              // b*C + o
    int b  = bo >> 8, o = bo & 255;
    int i  = threadIdx.x;

    float w1   = W[o * (2 * C_) + i];
    float w2   = W[o * (2 * C_) + C_ + i];
    float rin  = g_rin [b * C_ + i];
    float muin = g_muin[b * C_ + i];
    float rln  = g_rln [b];
    float muln = g_muln[b];
    float gamma = params[b * (2 * C_) + o];
    float beta  = params[b * (2 * C_) + C_ + o];

    float t = w1 * rin;
    g_M[(size_t)bo * C_ + i] = gamma * (t + w2 * rln);

    float pb = -(t * muin + w2 * rln * muln);
    float tot = blockReduceSum(pb);
    if (threadIdx.x == 0) g_d[bo] = gamma * tot + beta;
}

// =====================================================================
// kernel 3: tensor-core GEMM  out[b] = M[b] * x[b] + d[b]
//   bf16 3-split:  M = Mh + Ml,  x = xh + xl
//   out ≈ Mh*xh + Mh*xl + Ml*xh      (fp32 accumulate, mma.m16n8k16)
// =====================================================================
#define BM 128
#define BN 128
#define BK 32
#define NKT (C_ / BK)       // 8

// per-stage smem layout (bytes): Ah | Al | Xh | Xl   (8 KB each)
#define SA_H  0
#define SA_L  8192
#define SX_H  16384
#define SX_L  24576
#define STAGE 32768         // 2 stages => 64 KB dynamic smem

// swizzled byte offsets (16B-chunk XOR swizzles; conflict-free for ldmatrix)
__device__ __forceinline__ int a_off(int r, int c) {      // r:0..127 row, c:0..3 chunk
    return r * 64 + ((c ^ ((r >> 1) & 3)) << 4);
}
__device__ __forceinline__ int x_off(int r, int c) {      // r:0..31 row, c:0..15 chunk
    return r * 256 + ((c ^ (r & 7)) << 4);
}

__device__ __forceinline__ uint32_t cvta_s(const void* p) {
    return (uint32_t)__cvta_generic_to_shared(p);
}
__device__ __forceinline__ void ldsm4(uint32_t a[4], uint32_t addr) {
    asm volatile("ldmatrix.sync.aligned.m8n8.x4.shared.b16 {%0,%1,%2,%3}, [%4];\n"
                 : "=r"(a[0]), "=r"(a[1]), "=r"(a[2]), "=r"(a[3]) : "r"(addr));
}
__device__ __forceinline__ void ldsm4t(uint32_t a[4], uint32_t addr) {
    asm volatile("ldmatrix.sync.aligned.m8n8.x4.trans.shared.b16 {%0,%1,%2,%3}, [%4];\n"
                 : "=r"(a[0]), "=r"(a[1]), "=r"(a[2]), "=r"(a[3]) : "r"(addr));
}
__device__ __forceinline__ void mma16816(float c[4], const uint32_t a[4],
                                         uint32_t b0, uint32_t b1) {
    asm volatile(
        "mma.sync.aligned.m16n8k16.row.col.f32.bf16.bf16.f32 "
        "{%0,%1,%2,%3},{%4,%5,%6,%7},{%8,%9},{%0,%1,%2,%3};\n"
        : "+f"(c[0]), "+f"(c[1]), "+f"(c[2]), "+f"(c[3])
        : "r"(a[0]), "r"(a[1]), "r"(a[2]), "r"(a[3]), "r"(b0), "r"(b1));
}

// 8 fp32 -> hi/lo bf16x8 packed in uint4 each
__device__ __forceinline__ void cvt8(float4 f0, float4 f1, uint4& hi, uint4& lo) {
    float f[8] = {f0.x, f0.y, f0.z, f0.w, f1.x, f1.y, f1.z, f1.w};
    uint32_t h[8], l[8];
    #pragma unroll
    for (int i = 0; i < 8; i++) {
        __nv_bfloat16 bh = __float2bfloat16(f[i]);
        float rem = f[i] - __bfloat162float(bh);
        __nv_bfloat16 bl = __float2bfloat16(rem);
        h[i] = (uint32_t)__bfloat16_as_ushort(bh);
        l[i] = (uint32_t)__bfloat16_as_ushort(bl);
    }
    hi = make_uint4(h[0] | (h[1] << 16), h[2] | (h[3] << 16),
                    h[4] | (h[5] << 16), h[6] | (h[7] << 16));
    lo = make_uint4(l[0] | (l[1] << 16), l[2] | (l[3] << 16),
                    l[4] | (l[5] << 16), l[6] | (l[7] << 16));
}

extern __shared__ char smem_raw[];

__global__ __launch_bounds__(256) void gemm_mma_kernel(const float* __restrict__ x,
                                                       float* __restrict__ out) {
    const int b  = blockIdx.z;
    const int mt = blockIdx.y;
    const int nt = blockIdx.x;
    const int t    = threadIdx.x;
    const int lane = t & 31;
    const int wid  = t >> 5;
    const int wm   = wid >> 1;   // 0..3 (m direction, 32 rows each)
    const int wn   = wid & 1;    // 0..1 (n direction, 64 cols each)

    char* sm = smem_raw;
    const float* Ab = g_M + ((size_t)b * C_ + mt * BM) * C_;
    const float* Bb = x + (size_t)b * CHW_ + (size_t)nt * BN;

    float4 ra[2][2], rx[2][2];   // prefetch regs (A: 8 floats x2 ids, X: same)

    auto gload = [&](int kt) {
        #pragma unroll
        for (int j = 0; j < 2; j++) {
            int id = t + 256 * j;
            int r = id >> 2, c = id & 3;                       // A chunk
            const float* p = Ab + (size_t)r * C_ + kt * BK + c * 8;
            ra[j][0] = *(const float4*)p;
            ra[j][1] = *(const float4*)(p + 4);
            int rr = id >> 4, cx = id & 15;                    // X chunk
            const float* q = Bb + (size_t)(kt * BK + rr) * HW_ + cx * 8;
            rx[j][0] = *(const float4*)q;
            rx[j][1] = *(const float4*)(q + 4);
        }
    };
    auto cstore = [&](int buf) {
        char* base = sm + buf * STAGE;
        #pragma unroll
        for (int j = 0; j < 2; j++) {
            int id = t + 256 * j;
            uint4 hi, lo;
            int r = id >> 2, c = id & 3;
            cvt8(ra[j][0], ra[j][1], hi, lo);
            int off = a_off(r, c);
            *(uint4*)(base + SA_H + off) = hi;
            *(uint4*)(base + SA_L + off) = lo;
            int rr = id >> 4, cx = id & 15;
            cvt8(rx[j][0], rx[j][1], hi, lo);
            int offx = x_off(rr, cx);
            *(uint4*)(base + SX_H + offx) = hi;
            *(uint4*)(base + SX_L + offx) = lo;
        }
    };

    float acc[2][8][4];
    #pragma unroll
    for (int mi = 0; mi < 2; mi++)
        #pragma unroll
        for (int j = 0; j < 8; j++)
            #pragma unroll
            for (int p = 0; p < 4; p++) acc[mi][j][p] = 0.f;

    gload(0);
    cstore(0);
    __syncthreads();

    int cur = 0;
    for (int kt = 0; kt < NKT; kt++) {
        if (kt + 1 < NKT) gload(kt + 1);
        char* base = sm + cur * STAGE;

        #pragma unroll
        for (int kk = 0; kk < 2; kk++) {      // two k16 steps per BK=32
            uint32_t ah[2][4], al[2][4], xh[4][4], xl[4][4];
            #pragma unroll
            for (int mi = 0; mi < 2; mi++) {
                int r = wm * 32 + mi * 16 + (lane & 15);
                int c = kk * 2 + (lane >> 4);
                int off = a_off(r, c);
                ldsm4(ah[mi], cvta_s(base + SA_H + off));
                ldsm4(al[mi], cvta_s(base + SA_L + off));
            }
            #pragma unroll
            for (int ni = 0; ni < 4; ni++) {
                int r = kk * 16 + (lane & 15);
                int c = wn * 8 + ni * 2 + (lane >> 4);
                int off = x_off(r, c);
                ldsm4t(xh[ni], cvta_s(base + SX_H + off));
                ldsm4t(xl[ni], cvta_s(base + SX_L + off));
            }
            #pragma unroll
            for (int mi = 0; mi < 2; mi++)
                #pragma unroll
                for (int j = 0; j < 8; j++) {
                    int ni = j >> 1, h = (j & 1) * 2;
                    mma16816(acc[mi][j], ah[mi], xh[ni][h], xh[ni][h + 1]);
                    mma16816(acc[mi][j], ah[mi], xl[ni][h], xl[ni][h + 1]);
                    mma16816(acc[mi][j], al[mi], xh[ni][h], xh[ni][h + 1]);
                }
        }

        if (kt + 1 < NKT) {
            __syncthreads();
            cstore(cur ^ 1);
            __syncthreads();
            cur ^= 1;
        }
    }

    // epilogue: add fused bias, store (float2 per frag row-pair; 32B/4-lane sectors)
    const int o0 = mt * BM + wm * 32;
    const int n0 = nt * BN + wn * 64;
    float* outp = out + (size_t)b * CHW_;
    #pragma unroll
    for (int mi = 0; mi < 2; mi++) {
        int r0 = o0 + mi * 16 + (lane >> 2);
        float d0 = g_d[b * C_ + r0];
        float d1 = g_d[b * C_ + r0 + 8];
        #pragma unroll
        for (int j = 0; j < 8; j++) {
            int nn = n0 + j * 8 + (lane & 3) * 2;
            float2 v0 = make_float2(acc[mi][j][0] + d0, acc[mi][j][1] + d0);
            float2 v1 = make_float2(acc[mi][j][2] + d1, acc[mi][j][3] + d1);
            *(float2*)(outp + (size_t)r0 * HW_ + nn)       = v0;
            *(float2*)(outp + (size_t)(r0 + 8) * HW_ + nn) = v1;
        }
    }
}

// ---------------- launcher ----------------
extern "C" void kernel_launch(void* const* d_in, const int* in_sizes, int n_in,
                              void* d_out, int out_size) {
    const float* x      = (const float*)d_in[0];   // [8,256,128,128]
    const float* params = (const float*)d_in[1];   // [8,512]
    const float* W      = (const float*)d_in[2];   // [256,512]
    float* out          = (float*)d_out;           // [8,256,128,128]

    cudaFuncSetAttribute(gemm_mma_kernel,
                         cudaFuncAttributeMaxDynamicSharedMemorySize, 2 * STAGE);

    stats_kernel      <<<B_ * C_, 256>>>(x);
    batch_stats_kernel<<<B_,      256>>>();
    build_M_kernel    <<<B_ * C_, 256>>>(params, W);

    dim3 grid(HW_ / BN, C_ / BM, B_);              // (128, 2, 8)
    gemm_mma_kernel<<<grid, 256, 2 * STAGE>>>(x, out);
}